// round 16
// baseline (speedup 1.0000x reference)
#include <cuda_runtime.h>
#include <cuda_fp16.h>
#include <math.h>

// ---------------- scratch (device globals; no allocation allowed) ----------
#define MAXN 50000
#define MAXE 800000
#define NG   128
#define INF_ 128
#define HID  64
#define OUTF 32

__device__ unsigned long long g_degcnt[MAXN];  // hi32 = indeg, lo32 = ew*4096
__device__ float   g_dinv[MAXN];
__device__ __half2 g_h[(size_t)MAXN * 32];     // x @ W, fp16 storage
__device__ int     g_indeg[MAXN];
__device__ int     g_off[MAXN];
__device__ int     g_cursor[MAXN];
__device__ float2  g_csr[MAXE];                // (.x = bitcast src, .y = dinv[src]*ew)
__device__ int     g_blocksum[256];
__device__ int     g_gstart[NG + 1];
__device__ float   g_sums[NG * HID];
__device__ int     g_pool_cnt[NG];
__device__ volatile unsigned g_bar[8];
__device__ int     g_is64;

__device__ __forceinline__ int load_idx(const void* p, long long i) {
    if (g_is64) return (int)((const long long*)p)[i];
    return ((const int*)p)[i];
}

__device__ __forceinline__ void gbar(int id, unsigned target) {
    __syncthreads();
    if (threadIdx.x == 0) {
        __threadfence();
        atomicAdd((unsigned*)&g_bar[id], 1u);
        while (g_bar[id] < target) __nanosleep(64);
        __threadfence();
    }
    __syncthreads();
}

// ---------------- K1: init + dtype detect -----------------------------------
__global__ void k_prep(const int* __restrict__ ei_w, int N) {
    int i = blockIdx.x * blockDim.x + threadIdx.x;
    if (i < N)        g_degcnt[i] = 0ull;
    if (i < NG * HID) g_sums[i] = 0.0f;
    if (i < NG)       g_pool_cnt[i] = 0;
    if (i < 8)        *(unsigned*)&g_bar[i] = 0u;
    if (blockIdx.x == 0) {
        __shared__ int any_nonzero;
        if (threadIdx.x == 0) any_nonzero = 0;
        __syncthreads();
        for (int j = threadIdx.x; j < 1024; j += blockDim.x)
            if (ei_w[2 * j + 1] != 0) atomicOr(&any_nonzero, 1);
        __syncthreads();
        if (threadIdx.x == 0) g_is64 = any_nonzero ? 0 : 1;
    }
}

// ---------------- K2: persistent mega kernel --------------------------------
#define SM_BYTES (64 * 33 * 8 + 32 * 64 * 4)   // 25088 B
__global__ __launch_bounds__(256) void k_mega(
    const float* __restrict__ x, const float* __restrict__ W,
    const void* __restrict__ ei, const float* __restrict__ ew,
    const void* __restrict__ batch, const float* __restrict__ b,
    const float* __restrict__ W1, const float* __restrict__ b1,
    float* __restrict__ out_node, float* __restrict__ out_graph,
    int N, int E) {
    __shared__ char sm[SM_BYTES];
    const int nc = gridDim.x;
    const int ntiles = (N + 63) >> 6;
    // REBALANCED: ~1/3 of CTAs to GEMM (4 tiles each), ~2/3 to the
    // latency-bound graph chain (deg/fill scale with warp count).
    int ng = (ntiles + 3) >> 2;
    if (ng > (nc * 2) / 3) ng = (nc * 2) / 3;
    const int n_gemm = ng;
    const int n_graph = nc - n_gemm;
    const int bid = blockIdx.x;
    const int t = threadIdx.x;

    if (bid < n_gemm) {
        // ================= GEMM class =================
        float2* xs = (float2*)sm;                         // [64][33]
        float*  Ws = (float*)(sm + 64 * 33 * 8);          // [32][64]
        const int ty = t >> 4, tx = t & 15;
        for (int tile = bid; tile < ntiles; tile += n_gemm) {
            const int row0 = tile * 64;
            unsigned long long acc[4][2];
#pragma unroll
            for (int i = 0; i < 4; i++) { acc[i][0] = 0ull; acc[i][1] = 0ull; }
#pragma unroll
            for (int ch = 0; ch < 4; ch++) {
                for (int i = t; i < 512; i += 256) {
                    int k = i >> 4, c4 = i & 15;
                    *(float4*)&Ws[k * 64 + c4 * 4] =
                        *(const float4*)(W + (size_t)(ch * 32 + k) * HID + c4 * 4);
                }
                for (int i = t; i < 512; i += 256) {
                    int r = i >> 3, k4 = i & 7;
                    float4 v = make_float4(0.f, 0.f, 0.f, 0.f);
                    if (row0 + r < N)
                        v = *(const float4*)(x + (size_t)(row0 + r) * INF_ + ch * 32 + k4 * 4);
                    float2* xr = xs + r * 33;
                    xr[k4 * 4 + 0] = make_float2(v.x, v.x);
                    xr[k4 * 4 + 1] = make_float2(v.y, v.y);
                    xr[k4 * 4 + 2] = make_float2(v.z, v.z);
                    xr[k4 * 4 + 3] = make_float2(v.w, v.w);
                }
                __syncthreads();
#pragma unroll 8
                for (int k = 0; k < 32; k++) {
                    union { float4 v; unsigned long long u[2]; } w;
                    w.v = *(float4*)&Ws[k * 64 + tx * 4];
#pragma unroll
                    for (int i = 0; i < 4; i++) {
                        unsigned long long a =
                            *(unsigned long long*)&xs[(ty * 4 + i) * 33 + k];
                        asm("fma.rn.f32x2 %0, %1, %2, %0;"
                            : "+l"(acc[i][0]) : "l"(a), "l"(w.u[0]));
                        asm("fma.rn.f32x2 %0, %1, %2, %0;"
                            : "+l"(acc[i][1]) : "l"(a), "l"(w.u[1]));
                    }
                }
                __syncthreads();
            }
#pragma unroll
            for (int i = 0; i < 4; i++) {
                int row = row0 + ty * 4 + i;
                if (row < N) {
                    union { unsigned long long u; float2 f; } c0, c1;
                    c0.u = acc[i][0]; c1.u = acc[i][1];
                    union { __half2 h[2]; uint2 u; } pk;
                    pk.h[0] = __floats2half2_rn(c0.f.x, c0.f.y);
                    pk.h[1] = __floats2half2_rn(c1.f.x, c1.f.y);
                    *(uint2*)&g_h[(size_t)row * 32 + tx * 2] = pk.u;
                }
            }
        }
        gbar(2, (unsigned)nc);   // join
    } else {
        // ================= graph class =================
        const int gb = bid - n_gemm;
        const int stride = n_graph * 256;
        // --- packed deg+count histogram (one u64 atomic per edge, x2 MLP) ---
        for (int e = gb * 256 + t; e < E; e += 2 * stride) {
            int e2 = e + stride;
            bool has2 = e2 < E;
            int d1 = load_idx(ei, (long long)E + e);
            float w1 = ew[e];
            int d2 = 0; float w2 = 0.0f;
            if (has2) { d2 = load_idx(ei, (long long)E + e2); w2 = ew[e2]; }
            unsigned long long p1 =
                (1ull << 32) | (unsigned)__float2int_rn(w1 * 4096.0f);
            atomicAdd(&g_degcnt[d1], p1);
            if (has2) {
                unsigned long long p2 =
                    (1ull << 32) | (unsigned)__float2int_rn(w2 * 4096.0f);
                atomicAdd(&g_degcnt[d2], p2);
            }
        }
        gbar(0, (unsigned)n_graph);

        // --- scan phase A: per-tile block sums (no serial chain) ---
        {
            int* s = (int*)sm;   // [256]
            const int ntile = (N + 255) >> 8;
            for (int tile = gb; tile < ntile; tile += n_graph) {
                int i = tile * 256 + t;
                s[t] = (i < N) ? (int)(g_degcnt[i] >> 32) : 0;
                __syncthreads();
                for (int o = 128; o > 0; o >>= 1) {
                    if (t < o) s[t] += s[t + o];
                    __syncthreads();
                }
                if (t == 0) g_blocksum[tile] = s[0];
                __syncthreads();
            }
        }
        gbar(1, (unsigned)n_graph);

        // --- scan phase B: redundant smem scan of block sums + finish ---
        {
            int* bs = (int*)sm;              // [256]
            int* wsum = (int*)sm + 256;      // [8]
            const int ntile = (N + 255) >> 8;
            const int lane = t & 31, wid = t >> 5;
            bs[t] = (t < ntile) ? g_blocksum[t] : 0;
            __syncthreads();
            for (int o = 1; o < 256; o <<= 1) {
                int v2 = (t >= o) ? bs[t - o] : 0;
                __syncthreads();
                bs[t] += v2;
                __syncthreads();
            }
            for (int tile = gb; tile < ntile; tile += n_graph) {
                const int base = (tile > 0) ? bs[tile - 1] : 0;
                int i = tile * 256 + t;
                unsigned long long dc = (i < N) ? g_degcnt[i] : 0ull;
                int v = (int)(dc >> 32);
                int xv = v;
#pragma unroll
                for (int o = 1; o < 32; o <<= 1) {
                    int y = __shfl_up_sync(0xffffffffu, xv, o);
                    if (lane >= o) xv += y;
                }
                if (lane == 31) wsum[wid] = xv;
                __syncthreads();
                if (t < 32) {
                    int s2 = (t < 8) ? wsum[t] : 0;
#pragma unroll
                    for (int o = 1; o < 8; o <<= 1) {
                        int y = __shfl_up_sync(0xffffffffu, s2, o);
                        if (lane >= o) s2 += y;
                    }
                    if (t < 8) wsum[t] = s2;
                }
                __syncthreads();
                int incl = xv + (wid ? wsum[wid - 1] : 0);
                if (i < N) {
                    int excl = base + incl - v;
                    g_off[i]    = excl;
                    g_cursor[i] = excl;
                    g_indeg[i]  = v;
                    float dg = (float)(unsigned)(dc & 0xffffffffull) * (1.0f / 4096.0f);
                    g_dinv[i] = rsqrtf(1.0f + dg);
                    int bi = load_idx(batch, i);
                    int bp = (i == 0) ? -1 : load_idx(batch, i - 1);
                    for (int g = bp + 1; g <= bi; g++) g_gstart[g] = i;
                    if (i == N - 1)
                        for (int g = bi + 1; g <= NG; g++) g_gstart[g] = N;
                }
                __syncthreads();
            }
        }
        gbar(5, (unsigned)n_graph);

        // --- CSR fill (graph class only, x2 unrolled) ---
        for (int e = gb * 256 + t; e < E; e += 2 * stride) {
            int e2 = e + stride;
            bool has2 = e2 < E;
            int s1 = load_idx(ei, e);
            int d1 = load_idx(ei, (long long)E + e);
            float w1 = ew[e];
            int s2 = 0, d2 = 0; float w2 = 0.0f;
            if (has2) {
                s2 = load_idx(ei, e2);
                d2 = load_idx(ei, (long long)E + e2);
                w2 = ew[e2];
            }
            float v1 = g_dinv[s1] * w1;
            float v2 = has2 ? g_dinv[s2] * w2 : 0.0f;
            int p1 = atomicAdd(&g_cursor[d1], 1);
            int p2 = has2 ? atomicAdd(&g_cursor[d2], 1) : 0;
            g_csr[p1] = make_float2(__int_as_float(s1), v1);
            if (has2) g_csr[p2] = make_float2(__int_as_float(s2), v2);
        }
        gbar(2, (unsigned)nc);   // join
    }

    // ======== aggregate (all CTAs) — single warp/node, 8-wide gathers ========
    {
        float2* stage = (float2*)sm;   // [8][32]
        const int wid = t >> 5, lane = t & 31;
        const __half2* __restrict__ h2 = (const __half2*)g_h;
        const int ngrp = (N + 7) >> 3;
        for (int grp = bid; grp < ngrp; grp += nc) {
            int n = grp * 8 + wid;
            if (n < N) {
                int start = g_off[n];
                int deg   = g_indeg[n];
                float ax = 0.0f, ay = 0.0f;
                for (int base = 0; base < deg; base += 32) {
                    int j = base + lane;
                    if (j < deg) stage[wid * 32 + lane] = g_csr[start + j];
                    __syncwarp();
                    int m = min(32, deg - base);
                    int k = 0;
                    for (; k + 8 <= m; k += 8) {
                        float2 cw[8];
                        __half2 hv[8];
#pragma unroll
                        for (int u = 0; u < 8; u++) cw[u] = stage[wid * 32 + k + u];
#pragma unroll
                        for (int u = 0; u < 8; u++)
                            hv[u] = h2[(size_t)__float_as_int(cw[u].x) * 32 + lane];
#pragma unroll
                        for (int u = 0; u < 8; u++) {
                            float2 f = __half22float2(hv[u]);
                            ax += f.x * cw[u].y;
                            ay += f.y * cw[u].y;
                        }
                    }
                    for (; k + 4 <= m; k += 4) {
                        float2 cw[4];
                        __half2 hv[4];
#pragma unroll
                        for (int u = 0; u < 4; u++) cw[u] = stage[wid * 32 + k + u];
#pragma unroll
                        for (int u = 0; u < 4; u++)
                            hv[u] = h2[(size_t)__float_as_int(cw[u].x) * 32 + lane];
#pragma unroll
                        for (int u = 0; u < 4; u++) {
                            float2 f = __half22float2(hv[u]);
                            ax += f.x * cw[u].y;
                            ay += f.y * cw[u].y;
                        }
                    }
                    for (; k < m; k++) {
                        float2 cw = stage[wid * 32 + k];
                        float2 f = __half22float2(
                            h2[(size_t)__float_as_int(cw.x) * 32 + lane]);
                        ax += f.x * cw.y;
                        ay += f.y * cw.y;
                    }
                    __syncwarp();
                }
                float dv = g_dinv[n];
                float2 hn = __half22float2(h2[(size_t)n * 32 + lane]);
                float vx = dv * (ax + dv * hn.x) + b[lane * 2 + 0];
                float vy = dv * (ay + dv * hn.y) + b[lane * 2 + 1];
                ((float2*)out_node)[(size_t)n * 32 + lane] =
                    make_float2(tanhf(vx), tanhf(vy));
            }
        }
    }
    gbar(3, (unsigned)nc);

    // ================= pool (all CTAs, 512 tasks) =================
    {
        float* part = (float*)sm;
        int* s_last = (int*)(sm + 4 * 64 * 4);
        for (int task = bid; task < NG * 4; task += nc) {
            int g = task >> 2, chunk = task & 3;
            int lo = g_gstart[g], hi = g_gstart[g + 1];
            int col = t & 63, rg = t >> 6;
            float a = 0.0f;
            for (int r = lo + chunk * 4 + rg; r < hi; r += 16)
                a += out_node[(size_t)r * HID + col];
            part[rg * 64 + col] = a;
            __syncthreads();
            if (t < 64) {
                float s = part[t] + part[64 + t] + part[128 + t] + part[192 + t];
                if (s != 0.0f) atomicAdd(&g_sums[g * HID + t], s);
            }
            __threadfence();
            __syncthreads();
            if (t == 0) *s_last = (atomicAdd(&g_pool_cnt[g], 1) == 3) ? 1 : 0;
            __syncthreads();
            if (*s_last) {
                __threadfence();
                if (t < OUTF) {
                    float inv = 1.0f / fmaxf((float)(hi - lo), 1.0f);
                    float sum = b1[t];
#pragma unroll 8
                    for (int k = 0; k < HID; k++)
                        sum += (*(volatile float*)&g_sums[g * HID + k]) * inv *
                               W1[k * OUTF + t];
                    out_graph[g * OUTF + t] = tanhf(sum);
                }
            }
            __syncthreads();
        }
    }
}

// ---------------- launch -----------------------------------------------------

extern "C" void kernel_launch(void* const* d_in, const int* in_sizes, int n_in,
                              void* d_out, int out_size) {
    const float* x     = (const float*)d_in[0];
    const void*  ei    = d_in[1];
    const float* ew    = (const float*)d_in[2];
    const void*  batch = d_in[3];
    const float* W  = (const float*)d_in[5];
    const float* b  = (const float*)d_in[6];
    const float* W1 = (const float*)d_in[7];
    const float* b1 = (const float*)d_in[8];

    int N = in_sizes[0] / INF_;   // 50000
    int E = in_sizes[2];          // 800000

    float* out_graph = (float*)d_out;
    float* out_node  = (float*)d_out + NG * OUTF;

    int dev = 0;
    cudaGetDevice(&dev);
    int nsm = 0;
    cudaDeviceGetAttribute(&nsm, cudaDevAttrMultiProcessorCount, dev);
    if (nsm <= 0) nsm = 148;
    int occ = 0;
    cudaOccupancyMaxActiveBlocksPerMultiprocessor(&occ, k_mega, 256, 0);
    if (occ < 1) occ = 1;
    if (occ > 4) occ = 4;          // keep the proven 4-CTA/SM config
    int grid = nsm * occ;

    k_prep<<<(N + 255) / 256, 256>>>((const int*)ei, N);
    k_mega<<<grid, 256>>>(x, W, ei, ew, batch, b, W1, b1,
                          out_node, out_graph, N, E);
}

// round 17
// speedup vs baseline: 1.1585x; 1.1585x over previous
#include <cuda_runtime.h>
#include <cuda_fp16.h>
#include <math.h>

// ---------------- scratch (device globals; no allocation allowed) ----------
#define MAXN 50000
#define MAXE 800000
#define NG   128
#define INF_ 128
#define HID  64
#define OUTF 32

__device__ unsigned long long g_degcnt[MAXN];  // hi32 = indeg, lo32 = ew*4096
__device__ float   g_dinv[MAXN];
__device__ __half2 g_h[(size_t)MAXN * 32];     // x @ W, fp16 storage
__device__ int     g_indeg[MAXN];
__device__ int     g_off[MAXN];
__device__ int     g_cursor[MAXN];
__device__ float2  g_csr[MAXE];                // (.x = bitcast src, .y = dinv[src]*ew)
__device__ unsigned long long g_lookback[256];
__device__ int     g_gstart[NG + 1];
__device__ float   g_sums[NG * HID];
__device__ int     g_pool_cnt[NG];
__device__ volatile unsigned g_bar[8];
__device__ int     g_is64;

__device__ __forceinline__ int load_idx(const void* p, long long i) {
    if (g_is64) return (int)((const long long*)p)[i];
    return ((const int*)p)[i];
}

__device__ __forceinline__ float tanh_fast(float v) {
    float r;
    asm("tanh.approx.f32 %0, %1;" : "=f"(r) : "f"(v));
    return r;
}

__device__ __forceinline__ void gbar(int id, unsigned target) {
    __syncthreads();
    if (threadIdx.x == 0) {
        __threadfence();
        atomicAdd((unsigned*)&g_bar[id], 1u);
        while (g_bar[id] < target) __nanosleep(64);
        __threadfence();
    }
    __syncthreads();
}

// ---------------- K1: init + dtype detect -----------------------------------
__global__ void k_prep(const int* __restrict__ ei_w, int N) {
    int i = blockIdx.x * blockDim.x + threadIdx.x;
    if (i < N)        g_degcnt[i] = 0ull;
    if (i < NG * HID) g_sums[i] = 0.0f;
    if (i < NG)       g_pool_cnt[i] = 0;
    if (i < 256)      g_lookback[i] = 0ull;
    if (i < 8)        *(unsigned*)&g_bar[i] = 0u;
    if (blockIdx.x == 0) {
        __shared__ int any_nonzero;
        if (threadIdx.x == 0) any_nonzero = 0;
        __syncthreads();
        for (int j = threadIdx.x; j < 1024; j += blockDim.x)
            if (ei_w[2 * j + 1] != 0) atomicOr(&any_nonzero, 1);
        __syncthreads();
        if (threadIdx.x == 0) g_is64 = any_nonzero ? 0 : 1;
    }
}

// ---------------- K2: persistent mega kernel --------------------------------
#define SM_BYTES (64 * 33 * 8 + 32 * 64 * 4)
__global__ __launch_bounds__(256) void k_mega(
    const float* __restrict__ x, const float* __restrict__ W,
    const void* __restrict__ ei, const float* __restrict__ ew,
    const void* __restrict__ batch, const float* __restrict__ b,
    const float* __restrict__ W1, const float* __restrict__ b1,
    float* __restrict__ out_node, float* __restrict__ out_graph,
    int N, int E) {
    __shared__ char sm[SM_BYTES];
    const int nc = gridDim.x;
    const int ntiles = (N + 63) >> 6;
    int ng = (ntiles + 1) >> 1;              // exactly 2 tiles per gemm CTA
    if (ng > (nc * 2) / 3) ng = (nc * 3) / 5;
    const int n_gemm = ng;
    const int n_graph = nc - n_gemm;
    const int bid = blockIdx.x;
    const int t = threadIdx.x;

    if (bid < n_gemm) {
        // ================= GEMM class =================
        float2* xs = (float2*)sm;                         // [64][33]
        float*  Ws = (float*)(sm + 64 * 33 * 8);          // [32][64]
        const int ty = t >> 4, tx = t & 15;
        for (int tile = bid; tile < ntiles; tile += n_gemm) {
            const int row0 = tile * 64;
            unsigned long long acc[4][2];
#pragma unroll
            for (int i = 0; i < 4; i++) { acc[i][0] = 0ull; acc[i][1] = 0ull; }
#pragma unroll
            for (int ch = 0; ch < 4; ch++) {
                for (int i = t; i < 512; i += 256) {
                    int k = i >> 4, c4 = i & 15;
                    *(float4*)&Ws[k * 64 + c4 * 4] =
                        *(const float4*)(W + (size_t)(ch * 32 + k) * HID + c4 * 4);
                }
                for (int i = t; i < 512; i += 256) {
                    int r = i >> 3, k4 = i & 7;
                    float4 v = make_float4(0.f, 0.f, 0.f, 0.f);
                    if (row0 + r < N)
                        v = *(const float4*)(x + (size_t)(row0 + r) * INF_ + ch * 32 + k4 * 4);
                    float2* xr = xs + r * 33;
                    xr[k4 * 4 + 0] = make_float2(v.x, v.x);
                    xr[k4 * 4 + 1] = make_float2(v.y, v.y);
                    xr[k4 * 4 + 2] = make_float2(v.z, v.z);
                    xr[k4 * 4 + 3] = make_float2(v.w, v.w);
                }
                __syncthreads();
#pragma unroll 8
                for (int k = 0; k < 32; k++) {
                    union { float4 v; unsigned long long u[2]; } w;
                    w.v = *(float4*)&Ws[k * 64 + tx * 4];
#pragma unroll
                    for (int i = 0; i < 4; i++) {
                        unsigned long long a =
                            *(unsigned long long*)&xs[(ty * 4 + i) * 33 + k];
                        asm("fma.rn.f32x2 %0, %1, %2, %0;"
                            : "+l"(acc[i][0]) : "l"(a), "l"(w.u[0]));
                        asm("fma.rn.f32x2 %0, %1, %2, %0;"
                            : "+l"(acc[i][1]) : "l"(a), "l"(w.u[1]));
                    }
                }
                __syncthreads();
            }
#pragma unroll
            for (int i = 0; i < 4; i++) {
                int row = row0 + ty * 4 + i;
                if (row < N) {
                    union { unsigned long long u; float2 f; } c0, c1;
                    c0.u = acc[i][0]; c1.u = acc[i][1];
                    union { __half2 h[2]; uint2 u; } pk;
                    pk.h[0] = __floats2half2_rn(c0.f.x, c0.f.y);
                    pk.h[1] = __floats2half2_rn(c1.f.x, c1.f.y);
                    *(uint2*)&g_h[(size_t)row * 32 + tx * 2] = pk.u;
                }
            }
        }
        gbar(2, (unsigned)nc);   // join
    } else {
        // ================= graph class =================
        const int gb = bid - n_gemm;
        const int stride = n_graph * 256;
        // --- packed deg+count histogram (one u64 atomic per edge, x2 MLP) ---
        for (int e = gb * 256 + t; e < E; e += 2 * stride) {
            int e2 = e + stride;
            bool has2 = e2 < E;
            int d1 = load_idx(ei, (long long)E + e);
            float w1 = ew[e];
            int d2 = 0; float w2 = 0.0f;
            if (has2) { d2 = load_idx(ei, (long long)E + e2); w2 = ew[e2]; }
            unsigned long long p1 =
                (1ull << 32) | (unsigned)__float2int_rn(w1 * 4096.0f);
            atomicAdd(&g_degcnt[d1], p1);
            if (has2) {
                unsigned long long p2 =
                    (1ull << 32) | (unsigned)__float2int_rn(w2 * 4096.0f);
                atomicAdd(&g_degcnt[d2], p2);
            }
        }
        gbar(0, (unsigned)n_graph);

        // --- decoupled-lookback scan + dinv + graph bounds ---
        {
            int* wsum = (int*)sm;
            int* s_excl = (int*)sm + 8;
            const int ntile = (N + 255) >> 8;
            const int lane = t & 31, wid = t >> 5;
            for (int tile = gb; tile < ntile; tile += n_graph) {
                int i = tile * 256 + t;
                unsigned long long dc = (i < N) ? g_degcnt[i] : 0ull;
                int v = (int)(dc >> 32);
                int xv = v;
#pragma unroll
                for (int o = 1; o < 32; o <<= 1) {
                    int y = __shfl_up_sync(0xffffffffu, xv, o);
                    if (lane >= o) xv += y;
                }
                if (lane == 31) wsum[wid] = xv;
                __syncthreads();
                if (t < 32) {
                    int s2 = (t < 8) ? wsum[t] : 0;
#pragma unroll
                    for (int o = 1; o < 8; o <<= 1) {
                        int y = __shfl_up_sync(0xffffffffu, s2, o);
                        if (lane >= o) s2 += y;
                    }
                    if (t < 8) wsum[t] = s2;
                }
                __syncthreads();
                int incl = xv + (wid ? wsum[wid - 1] : 0);
                int total = wsum[7];
                if (t == 0) {
                    if (tile == 0) {
                        atomicExch(&g_lookback[0], (2ull << 32) | (unsigned)total);
                        *s_excl = 0;
                    } else {
                        atomicExch(&g_lookback[tile], (1ull << 32) | (unsigned)total);
                        int ex = 0;
                        int p = tile - 1;
                        while (true) {
                            unsigned long long w;
                            do {
                                w = *(volatile unsigned long long*)&g_lookback[p];
                                if ((w >> 32) == 0ull) __nanosleep(32);
                            } while ((w >> 32) == 0ull);
                            if ((w >> 32) == 2ull) { ex += (int)(unsigned)w; break; }
                            ex += (int)(unsigned)w;
                            p--;
                        }
                        atomicExch(&g_lookback[tile],
                                   (2ull << 32) | (unsigned)(ex + total));
                        *s_excl = ex;
                    }
                }
                __syncthreads();
                if (i < N) {
                    int excl = *s_excl + incl - v;
                    g_off[i]    = excl;
                    g_cursor[i] = excl;
                    g_indeg[i]  = v;
                    float dg = (float)(unsigned)(dc & 0xffffffffull) * (1.0f / 4096.0f);
                    g_dinv[i] = rsqrtf(1.0f + dg);
                    int bi = load_idx(batch, i);
                    int bp = (i == 0) ? -1 : load_idx(batch, i - 1);
                    for (int g = bp + 1; g <= bi; g++) g_gstart[g] = i;
                    if (i == N - 1)
                        for (int g = bi + 1; g <= NG; g++) g_gstart[g] = N;
                }
                __syncthreads();
            }
        }
        gbar(1, (unsigned)n_graph);

        // --- CSR fill (graph class only, x2 unrolled) ---
        for (int e = gb * 256 + t; e < E; e += 2 * stride) {
            int e2 = e + stride;
            bool has2 = e2 < E;
            int s1 = load_idx(ei, e);
            int d1 = load_idx(ei, (long long)E + e);
            float w1 = ew[e];
            int s2 = 0, d2 = 0; float w2 = 0.0f;
            if (has2) {
                s2 = load_idx(ei, e2);
                d2 = load_idx(ei, (long long)E + e2);
                w2 = ew[e2];
            }
            float v1 = g_dinv[s1] * w1;
            float v2 = has2 ? g_dinv[s2] * w2 : 0.0f;
            int p1 = atomicAdd(&g_cursor[d1], 1);
            int p2 = has2 ? atomicAdd(&g_cursor[d2], 1) : 0;
            g_csr[p1] = make_float2(__int_as_float(s1), v1);
            if (has2) g_csr[p2] = make_float2(__int_as_float(s2), v2);
        }
        gbar(2, (unsigned)nc);   // join
    }

    // ======== aggregate (all CTAs) — single warp/node, 8-wide gathers ========
    {
        float2* stage = (float2*)sm;   // [8][32]
        const int wid = t >> 5, lane = t & 31;
        const __half2* __restrict__ h2 = (const __half2*)g_h;
        const int ngrp = (N + 7) >> 3;
        for (int grp = bid; grp < ngrp; grp += nc) {
            int n = grp * 8 + wid;
            if (n < N) {
                int start = g_off[n];
                int deg   = g_indeg[n];
                float ax = 0.0f, ay = 0.0f;
                for (int base = 0; base < deg; base += 32) {
                    int j = base + lane;
                    if (j < deg) stage[wid * 32 + lane] = g_csr[start + j];
                    __syncwarp();
                    int m = min(32, deg - base);
                    int k = 0;
                    for (; k + 8 <= m; k += 8) {
                        float2 cw[8];
                        __half2 hv[8];
#pragma unroll
                        for (int u = 0; u < 8; u++) cw[u] = stage[wid * 32 + k + u];
#pragma unroll
                        for (int u = 0; u < 8; u++)
                            hv[u] = h2[(size_t)__float_as_int(cw[u].x) * 32 + lane];
#pragma unroll
                        for (int u = 0; u < 8; u++) {
                            float2 f = __half22float2(hv[u]);
                            ax += f.x * cw[u].y;
                            ay += f.y * cw[u].y;
                        }
                    }
                    for (; k + 4 <= m; k += 4) {
                        float2 cw[4];
                        __half2 hv[4];
#pragma unroll
                        for (int u = 0; u < 4; u++) cw[u] = stage[wid * 32 + k + u];
#pragma unroll
                        for (int u = 0; u < 4; u++)
                            hv[u] = h2[(size_t)__float_as_int(cw[u].x) * 32 + lane];
#pragma unroll
                        for (int u = 0; u < 4; u++) {
                            float2 f = __half22float2(hv[u]);
                            ax += f.x * cw[u].y;
                            ay += f.y * cw[u].y;
                        }
                    }
                    for (; k < m; k++) {
                        float2 cw = stage[wid * 32 + k];
                        float2 f = __half22float2(
                            h2[(size_t)__float_as_int(cw.x) * 32 + lane]);
                        ax += f.x * cw.y;
                        ay += f.y * cw.y;
                    }
                    __syncwarp();
                }
                float dv = g_dinv[n];
                float2 hn = __half22float2(h2[(size_t)n * 32 + lane]);
                float vx = dv * (ax + dv * hn.x) + b[lane * 2 + 0];
                float vy = dv * (ay + dv * hn.y) + b[lane * 2 + 1];
                ((float2*)out_node)[(size_t)n * 32 + lane] =
                    make_float2(tanh_fast(vx), tanh_fast(vy));
            }
        }
    }
    gbar(3, (unsigned)nc);

    // ================= pool (all CTAs, 512 tasks) =================
    {
        float* part = (float*)sm;
        int* s_last = (int*)(sm + 4 * 64 * 4);
        for (int task = bid; task < NG * 4; task += nc) {
            int g = task >> 2, chunk = task & 3;
            int lo = g_gstart[g], hi = g_gstart[g + 1];
            int col = t & 63, rg = t >> 6;
            float a = 0.0f;
            for (int r = lo + chunk * 4 + rg; r < hi; r += 16)
                a += out_node[(size_t)r * HID + col];
            part[rg * 64 + col] = a;
            __syncthreads();
            if (t < 64) {
                float s = part[t] + part[64 + t] + part[128 + t] + part[192 + t];
                if (s != 0.0f) atomicAdd(&g_sums[g * HID + t], s);
            }
            __threadfence();
            __syncthreads();
            if (t == 0) *s_last = (atomicAdd(&g_pool_cnt[g], 1) == 3) ? 1 : 0;
            __syncthreads();
            if (*s_last) {
                __threadfence();
                if (t < OUTF) {
                    float inv = 1.0f / fmaxf((float)(hi - lo), 1.0f);
                    float sum = b1[t];
#pragma unroll 8
                    for (int k = 0; k < HID; k++)
                        sum += (*(volatile float*)&g_sums[g * HID + k]) * inv *
                               W1[k * OUTF + t];
                    out_graph[g * OUTF + t] = tanh_fast(sum);
                }
            }
            __syncthreads();
        }
    }
}

// ---------------- launch -----------------------------------------------------

extern "C" void kernel_launch(void* const* d_in, const int* in_sizes, int n_in,
                              void* d_out, int out_size) {
    const float* x     = (const float*)d_in[0];
    const void*  ei    = d_in[1];
    const float* ew    = (const float*)d_in[2];
    const void*  batch = d_in[3];
    const float* W  = (const float*)d_in[5];
    const float* b  = (const float*)d_in[6];
    const float* W1 = (const float*)d_in[7];
    const float* b1 = (const float*)d_in[8];

    int N = in_sizes[0] / INF_;   // 50000
    int E = in_sizes[2];          // 800000

    float* out_graph = (float*)d_out;
    float* out_node  = (float*)d_out + NG * OUTF;

    int dev = 0;
    cudaGetDevice(&dev);
    int nsm = 0;
    cudaDeviceGetAttribute(&nsm, cudaDevAttrMultiProcessorCount, dev);
    if (nsm <= 0) nsm = 148;
    int occ = 0;
    cudaOccupancyMaxActiveBlocksPerMultiprocessor(&occ, k_mega, 256, 0);
    if (occ < 1) occ = 1;
    if (occ > 4) occ = 4;          // keep the proven 4-CTA/SM config
    int grid = nsm * occ;

    k_prep<<<(N + 255) / 256, 256>>>((const int*)ei, N);
    k_mega<<<grid, 256>>>(x, W, ei, ew, batch, b, W1, b1,
                          out_node, out_graph, N, E);
}